// round 2
// baseline (speedup 1.0000x reference)
#include <cuda_runtime.h>
#include <math.h>

#define NPIX 16384
#define WF 65
#define NF 8320
#define SMEM_FFT 75776

__device__ __align__(16) float2 g_xhat[(size_t)8 * 128 * NF];
__device__ __align__(16) float2 g_qkv [(size_t)8 * 384 * NF];
__device__ __align__(16) float  g_t   [(size_t)8 * 128 * NPIX];
__device__ __align__(16) float  g_attn[(size_t)8 * 128 * NPIX];

__device__ __forceinline__ float2 cadd(float2 a, float2 b){return make_float2(a.x+b.x,a.y+b.y);}
__device__ __forceinline__ float2 csub(float2 a, float2 b){return make_float2(a.x-b.x,a.y-b.y);}
__device__ __forceinline__ float2 cmul(float2 a, float2 b){return make_float2(a.x*b.x-a.y*b.y,a.x*b.y+a.y*b.x);}

// warp FFT-128 (e^{-i}, unnormalized). in: v[r]=x[lane+32r]. out: X[k], k=r+4*rev5(lane)
__device__ __forceinline__ void warp_fft128(float2 v[4], const float2* __restrict__ Tw, int lane){
    float2 t0=cadd(v[0],v[2]), t1=csub(v[0],v[2]), t2=cadd(v[1],v[3]), t3=csub(v[1],v[3]);
    v[0]=cadd(t0,t2); v[2]=csub(t0,t2);
    v[1]=make_float2(t1.x+t3.y, t1.y-t3.x);
    v[3]=make_float2(t1.x-t3.y, t1.y+t3.x);
    v[1]=cmul(v[1],Tw[lane]); v[2]=cmul(v[2],Tw[(2*lane)&127]); v[3]=cmul(v[3],Tw[(3*lane)&127]);
#pragma unroll
    for(int h=16;h>=1;h>>=1){
        float2 w=Tw[(lane&(h-1))*(64/h)];
#pragma unroll
        for(int r=0;r<4;r++){
            float2 b;
            b.x=__shfl_xor_sync(0xffffffffu,v[r].x,h);
            b.y=__shfl_xor_sync(0xffffffffu,v[r].y,h);
            if(lane&h) v[r]=cmul(csub(b,v[r]),w); else v[r]=cadd(v[r],b);
        }
    }
}

__device__ __forceinline__ void fill_tw(float2* Tw, int tid){
    if(tid<128){ float s,c; sincospif(-(float)tid/64.0f,&s,&c); Tw[tid]=make_float2(c,s); }
}

// forward rfft2 of real [128][128] plane -> half spectrum dst[wf*128+hf]
__global__ __launch_bounds__(256) void fwd_rfft2_kernel(const float* __restrict__ src, float2* __restrict__ dst){
    extern __shared__ float sm[];
    float* FBr=sm; float* FBi=FBr+8320;
    float2* Zt=(float2*)(FBi+8320); float2* Tw=Zt+8*128;
    const int p=blockIdx.x, tid=threadIdx.x, lane=tid&31, wid=tid>>5;
    fill_tw(Tw,tid); __syncthreads();
    const float* xp=src+(size_t)p*NPIX;
    float2* zw=Zt+wid*128;
    for(int rp=wid;rp<64;rp+=8){
        int r0=2*rp, r1=r0+1;
        float2 v[4];
#pragma unroll
        for(int r=0;r<4;r++){ int j=lane+32*r; v[r]=make_float2(xp[r0*128+j],xp[r1*128+j]); }
        warp_fft128(v,Tw,lane);
        int rv=__brev(lane)>>27;
#pragma unroll
        for(int r=0;r<4;r++) zw[r+4*rv]=v[r];
        __syncwarp();
        for(int f=lane;f<WF;f+=32){
            float2 Zf=zw[f], Zm=zw[(128-f)&127];
            FBr[r0*WF+f]=0.5f*(Zf.x+Zm.x); FBi[r0*WF+f]=0.5f*(Zf.y-Zm.y);
            FBr[r1*WF+f]=0.5f*(Zf.y+Zm.y); FBi[r1*WF+f]=0.5f*(Zm.x-Zf.x);
        }
        __syncwarp();
    }
    __syncthreads();
    float2* dp=dst+(size_t)p*NF;
    for(int wf=wid;wf<WF;wf+=8){
        float2 v[4];
#pragma unroll
        for(int r=0;r<4;r++){ int hh=lane+32*r; v[r]=make_float2(FBr[hh*WF+wf],FBi[hh*WF+wf]); }
        warp_fft128(v,Tw,lane);
        int rv=__brev(lane)>>27;
#pragma unroll
        for(int r=0;r<4;r++) zw[r+4*rv]=v[r];
        __syncwarp();
        for(int j=lane;j<128;j+=32) dp[wf*128+j]=zw[j];
        __syncwarp();
    }
}

// out = irfft2_raw(conj(A)*B)*scale [* tmul]. plane p: b=p>>7, d=p&127.
__global__ __launch_bounds__(256) void inv_rfft2_kernel(const float2* __restrict__ Ab, const float2* __restrict__ Bb,
        int As,int Ao,int Bs,int Bo, const float* __restrict__ tmul, float* __restrict__ out, float scale){
    extern __shared__ float sm[];
    float* FBr=sm; float* FBi=FBr+8320;
    float2* Zt=(float2*)(FBi+8320); float2* Tw=Zt+8*128;
    const int p=blockIdx.x, b=p>>7, d=p&127;
    const int tid=threadIdx.x, lane=tid&31, wid=tid>>5;
    fill_tw(Tw,tid); __syncthreads();
    const float2* Ap=Ab+(size_t)(b*As+Ao+d)*NF;
    const float2* Bp=Bb+(size_t)(b*Bs+Bo+d)*NF;
    float2* zw=Zt+wid*128;
    // inverse along hf: ifft(M)=conj(fft(conj(M))); conj(conj(A)B)=A*conj(B)
    for(int wf=wid;wf<WF;wf+=8){
        float2 v[4];
#pragma unroll
        for(int r=0;r<4;r++){
            int fi=wf*128+lane+32*r;
            float2 a=Ap[fi], bb=Bp[fi];
            v[r]=make_float2(a.x*bb.x+a.y*bb.y, a.y*bb.x-a.x*bb.y); // A*conj(B)
        }
        warp_fft128(v,Tw,lane);
        int rv=__brev(lane)>>27;
#pragma unroll
        for(int r=0;r<4;r++){ int hh=r+4*rv; FBr[hh*WF+wf]=v[r].x; FBi[hh*WF+wf]=-v[r].y; }
    }
    __syncthreads();
    float* op=out+(size_t)p*NPIX;
    const float* tp=tmul?(tmul+(size_t)p*NPIX):(const float*)0;
    for(int rp=wid;rp<64;rp+=8){
        int h0=2*rp, h1=h0+1;
        float2 v[4];
#pragma unroll
        for(int r=0;r<4;r++){
            int f=lane+32*r;
            if(f<WF){
                float g0x=FBr[h0*WF+f],g0y=FBi[h0*WF+f],g1x=FBr[h1*WF+f],g1y=FBi[h1*WF+f];
                v[r]=make_float2(g0x-g1y, -g0y-g1x);       // conj(G0 + i*G1)
            }else{
                int m=128-f;
                float g0x=FBr[h0*WF+m],g0y=FBi[h0*WF+m],g1x=FBr[h1*WF+m],g1y=FBi[h1*WF+m];
                v[r]=make_float2(g0x+g1y, g0y-g1x);        // conj(conj(G0m)+i*conj(G1m))
            }
        }
        warp_fft128(v,Tw,lane);
        int rv=__brev(lane)>>27;
#pragma unroll
        for(int r=0;r<4;r++) zw[r+4*rv]=v[r];
        __syncwarp();
        for(int w=lane;w<128;w+=32){
            float2 z=zw[w];
            float o0=z.x*scale, o1=-z.y*scale;
            int i0=h0*128+w, i1=h1*128+w;
            if(tp){ o0*=tp[i0]; o1*=tp[i1]; }
            op[i0]=o0; op[i1]=o1;
        }
        __syncwarp();
    }
}

__global__ __launch_bounds__(256) void softmax_kernel(float* __restrict__ a){
    extern __shared__ float buf[];                 // 16384 floats
    __shared__ float red[16];
    float* p=a+(size_t)blockIdx.x*NPIX;
    int t=threadIdx.x;
    float4* p4=(float4*)p; float4* b4=(float4*)buf;
    float mx=-1e30f;
    for(int i=t;i<4096;i+=256){ float4 v=p4[i]; b4[i]=v; mx=fmaxf(mx,fmaxf(fmaxf(v.x,v.y),fmaxf(v.z,v.w))); }
    for(int o=16;o;o>>=1) mx=fmaxf(mx,__shfl_xor_sync(0xffffffffu,mx,o));
    if((t&31)==0) red[t>>5]=mx;
    __syncthreads();
    mx=red[0];
#pragma unroll
    for(int i=1;i<8;i++) mx=fmaxf(mx,red[i]);
    float s=0.f;
    for(int i=t;i<4096;i+=256){
        float4 v=b4[i];
        v.x=expf(v.x-mx); v.y=expf(v.y-mx); v.z=expf(v.z-mx); v.w=expf(v.w-mx);
        b4[i]=v; s+=v.x+v.y+v.z+v.w;
    }
    for(int o=16;o;o>>=1) s+=__shfl_xor_sync(0xffffffffu,s,o);
    if((t&31)==0) red[8+(t>>5)]=s;
    __syncthreads();
    s=0.f;
#pragma unroll
    for(int i=0;i<8;i++) s+=red[8+i];
    float inv=1.0f/s;
    for(int i=t;i<4096;i+=256){
        float4 v=b4[i]; v.x*=inv; v.y*=inv; v.z*=inv; v.w*=inv; p4[i]=v;
    }
}

// C[b][m][n] = W[m][k]*X[b][k][n] (+bias) (opt silu). K=128 fixed.
__global__ __launch_bounds__(256) void sgemm128(const float* __restrict__ W, const float* __restrict__ Xb,
        size_t xs, float* __restrict__ Cb, size_t cs, int ld, const float* __restrict__ bias, int act){
    __shared__ float Ws[8][132];
    __shared__ float Xs[8][128];
    const float* X=Xb+(size_t)blockIdx.z*xs;
    float* C=Cb+(size_t)blockIdx.z*cs;
    const int m0=blockIdx.y*128, n0=blockIdx.x*128;
    const int t=threadIdx.x, tx=t&15, ty=t>>4;
    float acc[8][8]={};
    for(int kk=0;kk<128;kk+=8){
#pragma unroll
        for(int i=0;i<4;i++){ int e=t+256*i, m=e>>3, k=e&7; Ws[k][m]=W[(size_t)(m0+m)*128+kk+k]; }
#pragma unroll
        for(int i=0;i<4;i++){ int e=t+256*i, n=e&127, k=e>>7; Xs[k][n]=X[(size_t)(kk+k)*ld+n0+n]; }
        __syncthreads();
#pragma unroll
        for(int k=0;k<8;k++){
            float wr[8],xr[8];
#pragma unroll
            for(int i=0;i<8;i++) wr[i]=Ws[k][ty*8+i];
#pragma unroll
            for(int j=0;j<8;j++) xr[j]=Xs[k][tx*8+j];
#pragma unroll
            for(int i=0;i<8;i++)
#pragma unroll
                for(int j=0;j<8;j++) acc[i][j]=fmaf(wr[i],xr[j],acc[i][j]);
        }
        __syncthreads();
    }
#pragma unroll
    for(int i=0;i<8;i++){
        int m=m0+ty*8+i;
        float bv=bias?bias[m]:0.f;
#pragma unroll
        for(int j=0;j<8;j++){
            float v=acc[i][j]+bv;
            if(act) v=v/(1.0f+expf(-v));
            C[(size_t)m*ld+n0+tx*8+j]=v;
        }
    }
}

extern "C" void kernel_launch(void* const* d_in, const int* in_sizes, int n_in, void* d_out, int out_size){
    const float* x     =(const float*)d_in[0];
    const float* w_qkv =(const float*)d_in[1];
    const float* w_gate=(const float*)d_in[2];
    const float* b_gate=(const float*)d_in[3];
    const float* w_proj=(const float*)d_in[4];
    const float* b_proj=(const float*)d_in[5];
    float* out=(float*)d_out;

    cudaFuncSetAttribute(fwd_rfft2_kernel, cudaFuncAttributeMaxDynamicSharedMemorySize, SMEM_FFT);
    cudaFuncSetAttribute(inv_rfft2_kernel, cudaFuncAttributeMaxDynamicSharedMemorySize, SMEM_FFT);
    cudaFuncSetAttribute(softmax_kernel,   cudaFuncAttributeMaxDynamicSharedMemorySize, 65536);

    float2* xhat; cudaGetSymbolAddress((void**)&xhat, g_xhat);
    float2* qkv;  cudaGetSymbolAddress((void**)&qkv,  g_qkv);
    float*  tg;   cudaGetSymbolAddress((void**)&tg,   g_t);
    float*  attn; cudaGetSymbolAddress((void**)&attn, g_attn);

    const size_t psN=(size_t)128*NPIX;       // plane-batch strides
    const size_t fsX=(size_t)128*2*NF;       // xhat floats per batch
    const size_t fsQ=(size_t)384*2*NF;
    dim3 thr(256);

    // 1. gate: t = silu(Wg x + bg)
    sgemm128<<<dim3(128,1,8),thr>>>(w_gate, x, psN, tg, psN, NPIX, b_gate, 1);
    // 2. x -> xhat
    fwd_rfft2_kernel<<<1024,thr,SMEM_FFT>>>(x, xhat);
    // 3. qkv = Wqkv @ xhat  (complex cols as 2*NF reals)
    sgemm128<<<dim3(130,3,8),thr>>>(w_qkv, (const float*)xhat, fsX, (float*)qkv, fsQ, 2*NF, 0, 0);
    // 4. attn = irfft2(conj(Q)K)/N^1.5
    inv_rfft2_kernel<<<1024,thr,SMEM_FFT>>>(qkv, qkv, 384,0, 384,128, 0, attn, 1.0f/2097152.0f);
    // 5. softmax over n
    softmax_kernel<<<1024,thr,65536>>>(attn);
    // 6. attn -> xhat (raw forward)
    fwd_rfft2_kernel<<<1024,thr,SMEM_FFT>>>(attn, xhat);
    // 7. gated = irfft2(conj(Ahat)V)/N * t
    inv_rfft2_kernel<<<1024,thr,SMEM_FFT>>>(xhat, qkv, 128,0, 384,256, tg, attn, 1.0f/16384.0f);
    // 8. out = Wp gated + bp
    sgemm128<<<dim3(128,1,8),thr>>>(w_proj, attn, psN, out, psN, NPIX, b_proj, 0);
}

// round 3
// speedup vs baseline: 1.9656x; 1.9656x over previous
#include <cuda_runtime.h>
#include <math.h>

#define NPIX 16384
#define WF 65
#define NF 8320
#define SMEM_FFT 75776

__device__ __align__(16) float2 g_xhat[(size_t)8 * 128 * NF];
__device__ __align__(16) float2 g_qkv [(size_t)8 * 384 * NF];
__device__ __align__(16) float  g_t   [(size_t)8 * 128 * NPIX];
__device__ __align__(16) float  g_attn[(size_t)8 * 128 * NPIX];

__device__ __forceinline__ float2 cadd(float2 a, float2 b){return make_float2(a.x+b.x,a.y+b.y);}
__device__ __forceinline__ float2 csub(float2 a, float2 b){return make_float2(a.x-b.x,a.y-b.y);}
__device__ __forceinline__ float2 cmul(float2 a, float2 b){return make_float2(a.x*b.x-a.y*b.y,a.x*b.y+a.y*b.x);}

// warp FFT-128 (e^{-i}, unnormalized). in: v[r]=x[lane+32r]. out: X[k], k=r+4*rev5(lane)
__device__ __forceinline__ void warp_fft128(float2 v[4], const float2* __restrict__ Tw, int lane){
    float2 t0=cadd(v[0],v[2]), t1=csub(v[0],v[2]), t2=cadd(v[1],v[3]), t3=csub(v[1],v[3]);
    v[0]=cadd(t0,t2); v[2]=csub(t0,t2);
    v[1]=make_float2(t1.x+t3.y, t1.y-t3.x);
    v[3]=make_float2(t1.x-t3.y, t1.y+t3.x);
    v[1]=cmul(v[1],Tw[lane]); v[2]=cmul(v[2],Tw[(2*lane)&127]); v[3]=cmul(v[3],Tw[(3*lane)&127]);
#pragma unroll
    for(int h=16;h>=1;h>>=1){
        float2 w=Tw[(lane&(h-1))*(64/h)];
#pragma unroll
        for(int r=0;r<4;r++){
            float2 b;
            b.x=__shfl_xor_sync(0xffffffffu,v[r].x,h);
            b.y=__shfl_xor_sync(0xffffffffu,v[r].y,h);
            if(lane&h) v[r]=cmul(csub(b,v[r]),w); else v[r]=cadd(v[r],b);
        }
    }
}

__device__ __forceinline__ void fill_tw(float2* Tw, int tid){
    if(tid<128){ float s,c; sincospif(-(float)tid/64.0f,&s,&c); Tw[tid]=make_float2(c,s); }
}

// forward rfft2 of real [128][128] plane -> half spectrum dst[wf*128+hf]
__global__ __launch_bounds__(256) void fwd_rfft2_kernel(const float* __restrict__ src, float2* __restrict__ dst){
    extern __shared__ float sm[];
    float* FBr=sm; float* FBi=FBr+8320;
    float2* Zt=(float2*)(FBi+8320); float2* Tw=Zt+8*128;
    const int p=blockIdx.x, tid=threadIdx.x, lane=tid&31, wid=tid>>5;
    fill_tw(Tw,tid); __syncthreads();
    const float* xp=src+(size_t)p*NPIX;
    float2* zw=Zt+wid*128;
    for(int rp=wid;rp<64;rp+=8){
        int r0=2*rp, r1=r0+1;
        float2 v[4];
#pragma unroll
        for(int r=0;r<4;r++){ int j=lane+32*r; v[r]=make_float2(xp[r0*128+j],xp[r1*128+j]); }
        warp_fft128(v,Tw,lane);
        int rv=__brev(lane)>>27;
#pragma unroll
        for(int r=0;r<4;r++) zw[r+4*rv]=v[r];
        __syncwarp();
        for(int f=lane;f<WF;f+=32){
            float2 Zf=zw[f], Zm=zw[(128-f)&127];
            FBr[r0*WF+f]=0.5f*(Zf.x+Zm.x); FBi[r0*WF+f]=0.5f*(Zf.y-Zm.y);
            FBr[r1*WF+f]=0.5f*(Zf.y+Zm.y); FBi[r1*WF+f]=0.5f*(Zm.x-Zf.x);
        }
        __syncwarp();
    }
    __syncthreads();
    float2* dp=dst+(size_t)p*NF;
    for(int wf=wid;wf<WF;wf+=8){
        float2 v[4];
#pragma unroll
        for(int r=0;r<4;r++){ int hh=lane+32*r; v[r]=make_float2(FBr[hh*WF+wf],FBi[hh*WF+wf]); }
        warp_fft128(v,Tw,lane);
        int rv=__brev(lane)>>27;
#pragma unroll
        for(int r=0;r<4;r++) zw[r+4*rv]=v[r];
        __syncwarp();
        for(int j=lane;j<128;j+=32) dp[wf*128+j]=zw[j];
        __syncwarp();
    }
}

// Fused: attn = irfft2(conj(Q)K)/N^1.5 ; softmax(n) ; Ah=rfft2(attn) ;
//        out = irfft2(conj(Ah)V)/N * t
__global__ __launch_bounds__(256) void fused_attn_kernel(const float2* __restrict__ qkvb,
        const float* __restrict__ tmul, float* __restrict__ out){
    extern __shared__ float sm[];
    float* FBr=sm; float* FBi=FBr+8320;
    float2* Zt=(float2*)(FBi+8320); float2* Tw=Zt+8*128;
    __shared__ float red[16];
    const int p=blockIdx.x, b=p>>7, d=p&127;
    const int tid=threadIdx.x, lane=tid&31, wid=tid>>5;
    fill_tw(Tw,tid); __syncthreads();
    const float2* Qp=qkvb+(size_t)(b*384      +d)*NF;
    const float2* Kp=qkvb+(size_t)(b*384+128  +d)*NF;
    const float2* Vp=qkvb+(size_t)(b*384+256  +d)*NF;
    float2* zw=Zt+wid*128;
    const int rv=__brev(lane)>>27;

    // Phase 1: inverse along hf of conj(Q)K: fft(Q*conj(K)), store conj into FB[hh][wf]
    for(int wf=wid;wf<WF;wf+=8){
        float2 v[4];
#pragma unroll
        for(int r=0;r<4;r++){
            int fi=wf*128+lane+32*r;
            float2 a=Qp[fi], bb=Kp[fi];
            v[r]=make_float2(a.x*bb.x+a.y*bb.y, a.y*bb.x-a.x*bb.y);
        }
        warp_fft128(v,Tw,lane);
#pragma unroll
        for(int r=0;r<4;r++){ int hh=r+4*rv; FBr[hh*WF+wf]=v[r].x; FBi[hh*WF+wf]=-v[r].y; }
    }
    __syncthreads();

    // Phase 2: inverse along w -> packed spatial (row h: w<65 in FBr[h][w], else FBi[h][w-65])
    const float s1=1.0f/2097152.0f;
    for(int rp=wid;rp<64;rp+=8){
        int h0=2*rp, h1=h0+1;
        float2 v[4];
#pragma unroll
        for(int r=0;r<4;r++){
            int f=lane+32*r;
            if(f<WF){
                float g0x=FBr[h0*WF+f],g0y=FBi[h0*WF+f],g1x=FBr[h1*WF+f],g1y=FBi[h1*WF+f];
                v[r]=make_float2(g0x-g1y, -g0y-g1x);
            }else{
                int m=128-f;
                float g0x=FBr[h0*WF+m],g0y=FBi[h0*WF+m],g1x=FBr[h1*WF+m],g1y=FBi[h1*WF+m];
                v[r]=make_float2(g0x+g1y, g0y-g1x);
            }
        }
        warp_fft128(v,Tw,lane);
#pragma unroll
        for(int r=0;r<4;r++) zw[r+4*rv]=v[r];
        __syncwarp();
        for(int w=lane;w<128;w+=32){
            float2 z=zw[w];
            float v0=z.x*s1, v1=-z.y*s1;
            if(w<WF){ FBr[h0*WF+w]=v0; FBr[h1*WF+w]=v1; }
            else    { FBi[h0*WF+w-WF]=v0; FBi[h1*WF+w-WF]=v1; }
        }
        __syncwarp();
    }
    __syncthreads();

    // Phase 3: softmax over all 16384 packed values
    float mx=-1e30f;
    for(int i=tid;i<NPIX;i+=256){
        int h=i>>7,w=i&127;
        float val=(w<WF)?FBr[h*WF+w]:FBi[h*WF+w-WF];
        mx=fmaxf(mx,val);
    }
    for(int o=16;o;o>>=1) mx=fmaxf(mx,__shfl_xor_sync(0xffffffffu,mx,o));
    if(lane==0) red[wid]=mx;
    __syncthreads();
    mx=red[0];
#pragma unroll
    for(int i=1;i<8;i++) mx=fmaxf(mx,red[i]);
    float s=0.f;
    for(int i=tid;i<NPIX;i+=256){
        int h=i>>7,w=i&127;
        float* a=(w<WF)?&FBr[h*WF+w]:&FBi[h*WF+w-WF];
        float e=expf(*a-mx); *a=e; s+=e;
    }
    for(int o=16;o;o>>=1) s+=__shfl_xor_sync(0xffffffffu,s,o);
    if(lane==0) red[8+wid]=s;
    __syncthreads();
    s=0.f;
#pragma unroll
    for(int i=0;i<8;i++) s+=red[8+i];
    float inv=1.0f/s;
    for(int i=tid;i<NPIX;i+=256){
        int h=i>>7,w=i&127;
        float* a=(w<WF)?&FBr[h*WF+w]:&FBi[h*WF+w-WF];
        *a*=inv;
    }
    __syncthreads();

    // Phase 4: forward along w (two-for-one) from packed spatial back into FB
    for(int rp=wid;rp<64;rp+=8){
        int r0=2*rp, r1=r0+1;
        float2 v[4];
#pragma unroll
        for(int r=0;r<4;r++){
            int j=lane+32*r;
            float a0=(j<WF)?FBr[r0*WF+j]:FBi[r0*WF+j-WF];
            float a1=(j<WF)?FBr[r1*WF+j]:FBi[r1*WF+j-WF];
            v[r]=make_float2(a0,a1);
        }
        warp_fft128(v,Tw,lane);
#pragma unroll
        for(int r=0;r<4;r++) zw[r+4*rv]=v[r];
        __syncwarp();
        for(int f=lane;f<WF;f+=32){
            float2 Zf=zw[f], Zm=zw[(128-f)&127];
            FBr[r0*WF+f]=0.5f*(Zf.x+Zm.x); FBi[r0*WF+f]=0.5f*(Zf.y-Zm.y);
            FBr[r1*WF+f]=0.5f*(Zf.y+Zm.y); FBi[r1*WF+f]=0.5f*(Zm.x-Zf.x);
        }
        __syncwarp();
    }
    __syncthreads();

    // Phase 5: per wf column: forward h-FFT, multiply conj(V), inverse h-FFT (conj trick)
    for(int wf=wid;wf<WF;wf+=8){
        float2 v[4];
#pragma unroll
        for(int r=0;r<4;r++){ int hh=lane+32*r; v[r]=make_float2(FBr[hh*WF+wf],FBi[hh*WF+wf]); }
        warp_fft128(v,Tw,lane);
#pragma unroll
        for(int r=0;r<4;r++) zw[r+4*rv]=v[r];
        __syncwarp();
#pragma unroll
        for(int r=0;r<4;r++){
            int k=lane+32*r;
            float2 A=zw[k], Vh=Vp[wf*128+k];
            v[r]=make_float2(A.x*Vh.x+A.y*Vh.y, A.y*Vh.x-A.x*Vh.y);
        }
        warp_fft128(v,Tw,lane);
#pragma unroll
        for(int r=0;r<4;r++){ int hh=r+4*rv; FBr[hh*WF+wf]=v[r].x; FBi[hh*WF+wf]=-v[r].y; }
        __syncwarp();
    }
    __syncthreads();

    // Phase 6: final inverse along w, scale 1/N, multiply gate t, write out
    const float s2=1.0f/16384.0f;
    float* op=out+(size_t)p*NPIX;
    const float* tp=tmul+(size_t)p*NPIX;
    for(int rp=wid;rp<64;rp+=8){
        int h0=2*rp, h1=h0+1;
        float2 v[4];
#pragma unroll
        for(int r=0;r<4;r++){
            int f=lane+32*r;
            if(f<WF){
                float g0x=FBr[h0*WF+f],g0y=FBi[h0*WF+f],g1x=FBr[h1*WF+f],g1y=FBi[h1*WF+f];
                v[r]=make_float2(g0x-g1y, -g0y-g1x);
            }else{
                int m=128-f;
                float g0x=FBr[h0*WF+m],g0y=FBi[h0*WF+m],g1x=FBr[h1*WF+m],g1y=FBi[h1*WF+m];
                v[r]=make_float2(g0x+g1y, g0y-g1x);
            }
        }
        warp_fft128(v,Tw,lane);
#pragma unroll
        for(int r=0;r<4;r++) zw[r+4*rv]=v[r];
        __syncwarp();
        for(int w=lane;w<128;w+=32){
            float2 z=zw[w];
            int i0=h0*128+w, i1=h1*128+w;
            op[i0]=z.x*s2*tp[i0];
            op[i1]=-z.y*s2*tp[i1];
        }
        __syncwarp();
    }
}

// C[b][m][n] = W[m][k]*X[b][k][n] (+bias)(opt silu). K=128, BK=16, pipelined.
__global__ __launch_bounds__(256) void sgemm128(const float* __restrict__ W, const float* __restrict__ Xb,
        size_t xs, float* __restrict__ Cb, size_t cs, int ld, const float* __restrict__ bias, int act){
    __shared__ float Ws[16][136];
    __shared__ float Xs[16][128];
    const float* X=Xb+(size_t)blockIdx.z*xs;
    float* C=Cb+(size_t)blockIdx.z*cs;
    const int m0=blockIdx.y*128, n0=blockIdx.x*128;
    const int t=threadIdx.x, tx=t&15, ty=t>>4;
    const int mW=t>>1, k8=(t&1)*8;
    const int kX0=t>>5, kX1=kX0+8, n40=t&31;
    const float* Wp=W+(size_t)(m0+mW)*128+k8;
    float4 w0,w1,x0,x1;
    w0=*(const float4*)(Wp+0); w1=*(const float4*)(Wp+4);
    x0=*(const float4*)&X[(size_t)kX0*ld+n0+n40*4];
    x1=*(const float4*)&X[(size_t)kX1*ld+n0+n40*4];
    float acc[8][8]={};
    for(int tile=0;tile<8;tile++){
        Ws[k8+0][mW]=w0.x; Ws[k8+1][mW]=w0.y; Ws[k8+2][mW]=w0.z; Ws[k8+3][mW]=w0.w;
        Ws[k8+4][mW]=w1.x; Ws[k8+5][mW]=w1.y; Ws[k8+6][mW]=w1.z; Ws[k8+7][mW]=w1.w;
        *(float4*)&Xs[kX0][n40*4]=x0;
        *(float4*)&Xs[kX1][n40*4]=x1;
        __syncthreads();
        if(tile<7){
            int kk=16*(tile+1);
            w0=*(const float4*)(Wp+kk); w1=*(const float4*)(Wp+kk+4);
            x0=*(const float4*)&X[(size_t)(kk+kX0)*ld+n0+n40*4];
            x1=*(const float4*)&X[(size_t)(kk+kX1)*ld+n0+n40*4];
        }
#pragma unroll
        for(int k=0;k<16;k++){
            float4 a0=*(float4*)&Ws[k][ty*8], a1=*(float4*)&Ws[k][ty*8+4];
            float4 b0=*(float4*)&Xs[k][tx*8], b1=*(float4*)&Xs[k][tx*8+4];
            float wr[8]={a0.x,a0.y,a0.z,a0.w,a1.x,a1.y,a1.z,a1.w};
            float xr[8]={b0.x,b0.y,b0.z,b0.w,b1.x,b1.y,b1.z,b1.w};
#pragma unroll
            for(int i=0;i<8;i++)
#pragma unroll
                for(int j=0;j<8;j++) acc[i][j]=fmaf(wr[i],xr[j],acc[i][j]);
        }
        __syncthreads();
    }
#pragma unroll
    for(int i=0;i<8;i++){
        int m=m0+ty*8+i;
        float bv=bias?bias[m]:0.f;
        float o[8];
#pragma unroll
        for(int j=0;j<8;j++){
            float v=acc[i][j]+bv;
            if(act) v=v/(1.0f+expf(-v));
            o[j]=v;
        }
        float* cp=&C[(size_t)m*ld+n0+tx*8];
        *(float4*)cp=make_float4(o[0],o[1],o[2],o[3]);
        *(float4*)(cp+4)=make_float4(o[4],o[5],o[6],o[7]);
    }
}

extern "C" void kernel_launch(void* const* d_in, const int* in_sizes, int n_in, void* d_out, int out_size){
    const float* x     =(const float*)d_in[0];
    const float* w_qkv =(const float*)d_in[1];
    const float* w_gate=(const float*)d_in[2];
    const float* b_gate=(const float*)d_in[3];
    const float* w_proj=(const float*)d_in[4];
    const float* b_proj=(const float*)d_in[5];
    float* out=(float*)d_out;

    cudaFuncSetAttribute(fwd_rfft2_kernel, cudaFuncAttributeMaxDynamicSharedMemorySize, SMEM_FFT);
    cudaFuncSetAttribute(fused_attn_kernel, cudaFuncAttributeMaxDynamicSharedMemorySize, SMEM_FFT);

    float2* xhat; cudaGetSymbolAddress((void**)&xhat, g_xhat);
    float2* qkv;  cudaGetSymbolAddress((void**)&qkv,  g_qkv);
    float*  tg;   cudaGetSymbolAddress((void**)&tg,   g_t);
    float*  attn; cudaGetSymbolAddress((void**)&attn, g_attn);

    const size_t psN=(size_t)128*NPIX;
    const size_t fsX=(size_t)128*2*NF;
    const size_t fsQ=(size_t)384*2*NF;
    dim3 thr(256);

    sgemm128<<<dim3(128,1,8),thr>>>(w_gate, x, psN, tg, psN, NPIX, b_gate, 1);
    fwd_rfft2_kernel<<<1024,thr,SMEM_FFT>>>(x, xhat);
    sgemm128<<<dim3(130,3,8),thr>>>(w_qkv, (const float*)xhat, fsX, (float*)qkv, fsQ, 2*NF, 0, 0);
    fused_attn_kernel<<<1024,thr,SMEM_FFT>>>(qkv, tg, attn);
    sgemm128<<<dim3(128,1,8),thr>>>(w_proj, attn, psN, out, psN, NPIX, b_proj, 0);
}

// round 6
// speedup vs baseline: 2.0371x; 1.0364x over previous
#include <cuda_runtime.h>
#include <cuda_bf16.h>
#include <math.h>
#include <stdint.h>

#define NPIX 16384
#define WF 65
#define NF 8320
#define SMEM_FFT 75776

__device__ __align__(16) float2   g_xhat[(size_t)8 * 128 * NF];
__device__ __align__(16) float2   g_qkv [(size_t)8 * 384 * NF];
__device__ __align__(16) float    g_t   [(size_t)8 * 128 * NPIX];
__device__ __align__(16) float    g_attn[(size_t)8 * 128 * NPIX];
__device__ __align__(16) uint32_t g_xt  [(size_t)8 * 16640 * 128];
__device__ __align__(16) uint32_t g_wpk [640 * 128];

__device__ __forceinline__ float2 cadd(float2 a, float2 b){return make_float2(a.x+b.x,a.y+b.y);}
__device__ __forceinline__ float2 csub(float2 a, float2 b){return make_float2(a.x-b.x,a.y-b.y);}
__device__ __forceinline__ float2 cmul(float2 a, float2 b){return make_float2(a.x*b.x-a.y*b.y,a.x*b.y+a.y*b.x);}

__device__ __forceinline__ void warp_fft128(float2 v[4], const float2* __restrict__ Tw, int lane){
    float2 t0=cadd(v[0],v[2]), t1=csub(v[0],v[2]), t2=cadd(v[1],v[3]), t3=csub(v[1],v[3]);
    v[0]=cadd(t0,t2); v[2]=csub(t0,t2);
    v[1]=make_float2(t1.x+t3.y, t1.y-t3.x);
    v[3]=make_float2(t1.x-t3.y, t1.y+t3.x);
    v[1]=cmul(v[1],Tw[lane]); v[2]=cmul(v[2],Tw[(2*lane)&127]); v[3]=cmul(v[3],Tw[(3*lane)&127]);
#pragma unroll
    for(int h=16;h>=1;h>>=1){
        float2 w=Tw[(lane&(h-1))*(64/h)];
#pragma unroll
        for(int r=0;r<4;r++){
            float2 b;
            b.x=__shfl_xor_sync(0xffffffffu,v[r].x,h);
            b.y=__shfl_xor_sync(0xffffffffu,v[r].y,h);
            if(lane&h) v[r]=cmul(csub(b,v[r]),w); else v[r]=cadd(v[r],b);
        }
    }
}
__device__ __forceinline__ void fill_tw(float2* Tw, int tid){
    if(tid<128){ float s,c; sincospif(-(float)tid/64.0f,&s,&c); Tw[tid]=make_float2(c,s); }
}

__global__ __launch_bounds__(256) void fwd_rfft2_kernel(const float* __restrict__ src, float2* __restrict__ dst){
    extern __shared__ float sm[];
    float* FBr=sm; float* FBi=FBr+8320;
    float2* Zt=(float2*)(FBi+8320); float2* Tw=Zt+8*128;
    const int p=blockIdx.x, tid=threadIdx.x, lane=tid&31, wid=tid>>5;
    fill_tw(Tw,tid); __syncthreads();
    const float* xp=src+(size_t)p*NPIX;
    float2* zw=Zt+wid*128;
    for(int rp=wid;rp<64;rp+=8){
        int r0=2*rp, r1=r0+1;
        float2 v[4];
#pragma unroll
        for(int r=0;r<4;r++){ int j=lane+32*r; v[r]=make_float2(xp[r0*128+j],xp[r1*128+j]); }
        warp_fft128(v,Tw,lane);
        int rv=__brev(lane)>>27;
#pragma unroll
        for(int r=0;r<4;r++) zw[r+4*rv]=v[r];
        __syncwarp();
        for(int f=lane;f<WF;f+=32){
            float2 Zf=zw[f], Zm=zw[(128-f)&127];
            FBr[r0*WF+f]=0.5f*(Zf.x+Zm.x); FBi[r0*WF+f]=0.5f*(Zf.y-Zm.y);
            FBr[r1*WF+f]=0.5f*(Zf.y+Zm.y); FBi[r1*WF+f]=0.5f*(Zm.x-Zf.x);
        }
        __syncwarp();
    }
    __syncthreads();
    float2* dp=dst+(size_t)p*NF;
    for(int wf=wid;wf<WF;wf+=8){
        float2 v[4];
#pragma unroll
        for(int r=0;r<4;r++){ int hh=lane+32*r; v[r]=make_float2(FBr[hh*WF+wf],FBi[hh*WF+wf]); }
        warp_fft128(v,Tw,lane);
        int rv=__brev(lane)>>27;
#pragma unroll
        for(int r=0;r<4;r++) zw[r+4*rv]=v[r];
        __syncwarp();
        for(int j=lane;j<128;j+=32) dp[wf*128+j]=zw[j];
        __syncwarp();
    }
}

__global__ __launch_bounds__(256) void fused_attn_kernel(const float2* __restrict__ qkvb,
        const float* __restrict__ tmul, float* __restrict__ out){
    extern __shared__ float sm[];
    float* FBr=sm; float* FBi=FBr+8320;
    float2* Zt=(float2*)(FBi+8320); float2* Tw=Zt+8*128;
    __shared__ float red[16];
    const int p=blockIdx.x, b=p>>7, d=p&127;
    const int tid=threadIdx.x, lane=tid&31, wid=tid>>5;
    fill_tw(Tw,tid); __syncthreads();
    const float2* Qp=qkvb+(size_t)(b*384      +d)*NF;
    const float2* Kp=qkvb+(size_t)(b*384+128  +d)*NF;
    const float2* Vp=qkvb+(size_t)(b*384+256  +d)*NF;
    float2* zw=Zt+wid*128;
    const int rv=__brev(lane)>>27;
    for(int wf=wid;wf<WF;wf+=8){
        float2 v[4];
#pragma unroll
        for(int r=0;r<4;r++){
            int fi=wf*128+lane+32*r;
            float2 a=Qp[fi], bb=Kp[fi];
            v[r]=make_float2(a.x*bb.x+a.y*bb.y, a.y*bb.x-a.x*bb.y);
        }
        warp_fft128(v,Tw,lane);
#pragma unroll
        for(int r=0;r<4;r++){ int hh=r+4*rv; FBr[hh*WF+wf]=v[r].x; FBi[hh*WF+wf]=-v[r].y; }
    }
    __syncthreads();
    const float s1=1.0f/2097152.0f;
    for(int rp=wid;rp<64;rp+=8){
        int h0=2*rp, h1=h0+1;
        float2 v[4];
#pragma unroll
        for(int r=0;r<4;r++){
            int f=lane+32*r;
            if(f<WF){
                float g0x=FBr[h0*WF+f],g0y=FBi[h0*WF+f],g1x=FBr[h1*WF+f],g1y=FBi[h1*WF+f];
                v[r]=make_float2(g0x-g1y, -g0y-g1x);
            }else{
                int m=128-f;
                float g0x=FBr[h0*WF+m],g0y=FBi[h0*WF+m],g1x=FBr[h1*WF+m],g1y=FBi[h1*WF+m];
                v[r]=make_float2(g0x+g1y, g0y-g1x);
            }
        }
        warp_fft128(v,Tw,lane);
#pragma unroll
        for(int r=0;r<4;r++) zw[r+4*rv]=v[r];
        __syncwarp();
        for(int w=lane;w<128;w+=32){
            float2 z=zw[w];
            float v0=z.x*s1, v1=-z.y*s1;
            if(w<WF){ FBr[h0*WF+w]=v0; FBr[h1*WF+w]=v1; }
            else    { FBi[h0*WF+w-WF]=v0; FBi[h1*WF+w-WF]=v1; }
        }
        __syncwarp();
    }
    __syncthreads();
    float mx=-1e30f;
    for(int i=tid;i<NPIX;i+=256){
        int h=i>>7,w=i&127;
        float val=(w<WF)?FBr[h*WF+w]:FBi[h*WF+w-WF];
        mx=fmaxf(mx,val);
    }
    for(int o=16;o;o>>=1) mx=fmaxf(mx,__shfl_xor_sync(0xffffffffu,mx,o));
    if(lane==0) red[wid]=mx;
    __syncthreads();
    mx=red[0];
#pragma unroll
    for(int i=1;i<8;i++) mx=fmaxf(mx,red[i]);
    float s=0.f;
    for(int i=tid;i<NPIX;i+=256){
        int h=i>>7,w=i&127;
        float* a=(w<WF)?&FBr[h*WF+w]:&FBi[h*WF+w-WF];
        float e=expf(*a-mx); *a=e; s+=e;
    }
    for(int o=16;o;o>>=1) s+=__shfl_xor_sync(0xffffffffu,s,o);
    if(lane==0) red[8+wid]=s;
    __syncthreads();
    s=0.f;
#pragma unroll
    for(int i=0;i<8;i++) s+=red[8+i];
    float inv=1.0f/s;
    for(int i=tid;i<NPIX;i+=256){
        int h=i>>7,w=i&127;
        float* a=(w<WF)?&FBr[h*WF+w]:&FBi[h*WF+w-WF];
        *a*=inv;
    }
    __syncthreads();
    for(int rp=wid;rp<64;rp+=8){
        int r0=2*rp, r1=r0+1;
        float2 v[4];
#pragma unroll
        for(int r=0;r<4;r++){
            int j=lane+32*r;
            float a0=(j<WF)?FBr[r0*WF+j]:FBi[r0*WF+j-WF];
            float a1=(j<WF)?FBr[r1*WF+j]:FBi[r1*WF+j-WF];
            v[r]=make_float2(a0,a1);
        }
        warp_fft128(v,Tw,lane);
#pragma unroll
        for(int r=0;r<4;r++) zw[r+4*rv]=v[r];
        __syncwarp();
        for(int f=lane;f<WF;f+=32){
            float2 Zf=zw[f], Zm=zw[(128-f)&127];
            FBr[r0*WF+f]=0.5f*(Zf.x+Zm.x); FBi[r0*WF+f]=0.5f*(Zf.y-Zm.y);
            FBr[r1*WF+f]=0.5f*(Zf.y+Zm.y); FBi[r1*WF+f]=0.5f*(Zm.x-Zf.x);
        }
        __syncwarp();
    }
    __syncthreads();
    for(int wf=wid;wf<WF;wf+=8){
        float2 v[4];
#pragma unroll
        for(int r=0;r<4;r++){ int hh=lane+32*r; v[r]=make_float2(FBr[hh*WF+wf],FBi[hh*WF+wf]); }
        warp_fft128(v,Tw,lane);
#pragma unroll
        for(int r=0;r<4;r++) zw[r+4*rv]=v[r];
        __syncwarp();
#pragma unroll
        for(int r=0;r<4;r++){
            int k=lane+32*r;
            float2 A=zw[k], Vh=Vp[wf*128+k];
            v[r]=make_float2(A.x*Vh.x+A.y*Vh.y, A.y*Vh.x-A.x*Vh.y);
        }
        warp_fft128(v,Tw,lane);
#pragma unroll
        for(int r=0;r<4;r++){ int hh=r+4*rv; FBr[hh*WF+wf]=v[r].x; FBi[hh*WF+wf]=-v[r].y; }
        __syncwarp();
    }
    __syncthreads();
    const float s2=1.0f/16384.0f;
    float* op=out+(size_t)p*NPIX;
    const float* tp=tmul+(size_t)p*NPIX;
    for(int rp=wid;rp<64;rp+=8){
        int h0=2*rp, h1=h0+1;
        float2 v[4];
#pragma unroll
        for(int r=0;r<4;r++){
            int f=lane+32*r;
            if(f<WF){
                float g0x=FBr[h0*WF+f],g0y=FBi[h0*WF+f],g1x=FBr[h1*WF+f],g1y=FBi[h1*WF+f];
                v[r]=make_float2(g0x-g1y, -g0y-g1x);
            }else{
                int m=128-f;
                float g0x=FBr[h0*WF+m],g0y=FBi[h0*WF+m],g1x=FBr[h1*WF+m],g1y=FBi[h1*WF+m];
                v[r]=make_float2(g0x+g1y, g0y-g1x);
            }
        }
        warp_fft128(v,Tw,lane);
#pragma unroll
        for(int r=0;r<4;r++) zw[r+4*rv]=v[r];
        __syncwarp();
        for(int w=lane;w<128;w+=32){
            float2 z=zw[w];
            int i0=h0*128+w, i1=h1*128+w;
            op[i0]=z.x*s2*tp[i0];
            op[i1]=-z.y*s2*tp[i1];
        }
        __syncwarp();
    }
}

// ---------------- bf16 split helpers ----------------
__device__ __forceinline__ uint32_t packsplit(float v){
    __nv_bfloat16 h=__float2bfloat16(v);
    float hf=__bfloat162float(h);
    __nv_bfloat16 l=__float2bfloat16(v-hf);
    return ((uint32_t)__bfloat16_as_ushort(h)<<16)|(uint32_t)__bfloat16_as_ushort(l);
}

__global__ __launch_bounds__(256) void tsplit(const float* __restrict__ src, size_t ss,
        uint32_t* __restrict__ dst, size_t ds, int L){
    __shared__ float tile[32][33];
    const float* sp=src+(size_t)blockIdx.z*ss;
    uint32_t* dp=dst+(size_t)blockIdx.z*ds;
    int c0=blockIdx.y*32, n0=blockIdx.x*32;
    int tx=threadIdx.x, ty=threadIdx.y;
    for(int r=ty;r<32;r+=8) tile[r][tx]=sp[(size_t)(c0+r)*L+n0+tx];
    __syncthreads();
    for(int r=ty;r<32;r+=8) dp[(size_t)(n0+r)*128+c0+tx]=packsplit(tile[tx][r]);
}

__global__ void wpack(const float* __restrict__ src, uint32_t* __restrict__ dst, int n){
    int i=blockIdx.x*256+threadIdx.x;
    if(i<n) dst[i]=packsplit(src[i]);
}

// ---------------- mma.sync bf16 GEMM (sm_80+ baseline PTX, no tcgen05) ----------------
#define HPAD 132
#define HSM_TOT (2*128*HPAD*4)

__device__ __forceinline__ void mma_bf16(float c[4], const uint32_t a[4], const uint32_t b[2]){
    asm volatile("mma.sync.aligned.m16n8k16.row.col.f32.bf16.bf16.f32 "
        "{%0,%1,%2,%3}, {%4,%5,%6,%7}, {%8,%9}, {%0,%1,%2,%3};"
        : "+f"(c[0]),"+f"(c[1]),"+f"(c[2]),"+f"(c[3])
        : "r"(a[0]),"r"(a[1]),"r"(a[2]),"r"(a[3]),"r"(b[0]),"r"(b[1]));
}
__device__ __forceinline__ void unpk(uint2 p, uint32_t& hi, uint32_t& lo){
    hi=(p.x>>16)|(p.y&0xFFFF0000u);
    lo=(p.x&0xFFFFu)|(p.y<<16);
}

// C[b][m][n] = W[m][k]*X[b][n][k]^T. W,X packed u32 (bf16hi<<16|bf16lo).
__global__ __launch_bounds__(256) void hgemm(const uint32_t* __restrict__ Wq,
        const uint32_t* __restrict__ Xt, size_t xs, float* __restrict__ Cb, size_t cs,
        int ld, const float* __restrict__ bias, int act){
    extern __shared__ uint32_t hsm[];
    uint32_t* Ws=hsm;                  // [128][HPAD]
    uint32_t* Xs=hsm+128*HPAD;         // [128][HPAD]
    const int b=blockIdx.z, mt=blockIdx.y, nt=blockIdx.x;
    const int tid=threadIdx.x, wid=tid>>5, lane=tid&31;
    const uint32_t* Wp=Wq+(size_t)mt*128*128;
    const uint32_t* Xp=Xt+(size_t)b*xs+(size_t)nt*128*128;
    for(int idx=tid;idx<4096;idx+=256){
        int row=idx>>5, c4=(idx&31)*4;
        uint4 w=*(const uint4*)&Wp[row*128+c4];
        *(uint4*)&Ws[row*HPAD+c4]=w;
        uint4 xv=*(const uint4*)&Xp[row*128+c4];
        *(uint4*)&Xs[row*HPAD+c4]=xv;
    }
    __syncthreads();

    const int g=lane>>2, t=lane&3;
    const int warp_m=(wid>>1)*32, warp_n=(wid&1)*64;
    float acc[2][8][4];
#pragma unroll
    for(int mi=0;mi<2;mi++)
#pragma unroll
        for(int ni=0;ni<8;ni++)
#pragma unroll
            for(int q=0;q<4;q++) acc[mi][ni][q]=0.f;

    for(int kk=0;kk<8;kk++){
        const int c0=kk*16+2*t, c1=c0+8;
        uint32_t bh[8][2], bl[8][2];
#pragma unroll
        for(int ni=0;ni<8;ni++){
            int n=warp_n+ni*8+g;
            unpk(*(uint2*)&Xs[n*HPAD+c0], bh[ni][0], bl[ni][0]);
            unpk(*(uint2*)&Xs[n*HPAD+c1], bh[ni][1], bl[ni][1]);
        }
#pragma unroll
        for(int mi=0;mi<2;mi++){
            int r0=warp_m+mi*16+g, r1=r0+8;
            uint32_t ah[4], al[4];
            unpk(*(uint2*)&Ws[r0*HPAD+c0], ah[0], al[0]);
            unpk(*(uint2*)&Ws[r1*HPAD+c0], ah[1], al[1]);
            unpk(*(uint2*)&Ws[r0*HPAD+c1], ah[2], al[2]);
            unpk(*(uint2*)&Ws[r1*HPAD+c1], ah[3], al[3]);
#pragma unroll
            for(int ni=0;ni<8;ni++){
                mma_bf16(acc[mi][ni], ah, bh[ni]);
                mma_bf16(acc[mi][ni], ah, bl[ni]);
                mma_bf16(acc[mi][ni], al, bh[ni]);
            }
        }
    }

    float* C=Cb+(size_t)b*cs+(size_t)(mt*128)*ld+(size_t)nt*128;
#pragma unroll
    for(int mi=0;mi<2;mi++){
        int m0=warp_m+mi*16+g, m1=m0+8;
        float bv0=bias?bias[mt*128+m0]:0.f;
        float bv1=bias?bias[mt*128+m1]:0.f;
#pragma unroll
        for(int ni=0;ni<8;ni++){
            int cn=warp_n+ni*8+2*t;
            float v0=acc[mi][ni][0]+bv0, v1=acc[mi][ni][1]+bv0;
            float v2=acc[mi][ni][2]+bv1, v3=acc[mi][ni][3]+bv1;
            if(act){
                v0=v0/(1.0f+expf(-v0)); v1=v1/(1.0f+expf(-v1));
                v2=v2/(1.0f+expf(-v2)); v3=v3/(1.0f+expf(-v3));
            }
            *(float2*)&C[(size_t)m0*ld+cn]=make_float2(v0,v1);
            *(float2*)&C[(size_t)m1*ld+cn]=make_float2(v2,v3);
        }
    }
}

extern "C" void kernel_launch(void* const* d_in, const int* in_sizes, int n_in, void* d_out, int out_size){
    const float* x     =(const float*)d_in[0];
    const float* w_qkv =(const float*)d_in[1];
    const float* w_gate=(const float*)d_in[2];
    const float* b_gate=(const float*)d_in[3];
    const float* w_proj=(const float*)d_in[4];
    const float* b_proj=(const float*)d_in[5];
    float* out=(float*)d_out;

    cudaFuncSetAttribute(fwd_rfft2_kernel, cudaFuncAttributeMaxDynamicSharedMemorySize, SMEM_FFT);
    cudaFuncSetAttribute(fused_attn_kernel, cudaFuncAttributeMaxDynamicSharedMemorySize, SMEM_FFT);
    cudaFuncSetAttribute(hgemm, cudaFuncAttributeMaxDynamicSharedMemorySize, HSM_TOT);

    float2* xhat; cudaGetSymbolAddress((void**)&xhat, g_xhat);
    float2* qkv;  cudaGetSymbolAddress((void**)&qkv,  g_qkv);
    float*  tg;   cudaGetSymbolAddress((void**)&tg,   g_t);
    float*  attn; cudaGetSymbolAddress((void**)&attn, g_attn);
    uint32_t* xt; cudaGetSymbolAddress((void**)&xt,   g_xt);
    uint32_t* wp; cudaGetSymbolAddress((void**)&wp,   g_wpk);

    uint32_t* wq=wp;
    uint32_t* wg=wp+384*128;
    uint32_t* wpj=wp+512*128;

    const size_t psN=(size_t)128*NPIX;
    const size_t fsQ=(size_t)384*2*NF;
    const size_t xsN=(size_t)NPIX*128, xsF=(size_t)16640*128;
    dim3 thr(256), tt(32,8);

    wpack<<<192,256>>>(w_qkv, wq, 384*128);
    wpack<<<64,256>>>(w_gate, wg, 128*128);
    wpack<<<64,256>>>(w_proj, wpj, 128*128);

    tsplit<<<dim3(512,4,8),tt>>>(x, psN, xt, xsN, NPIX);
    hgemm<<<dim3(128,1,8),thr,HSM_TOT>>>(wg, xt, xsN, tg, psN, NPIX, b_gate, 1);
    fwd_rfft2_kernel<<<1024,thr,SMEM_FFT>>>(x, xhat);
    tsplit<<<dim3(520,4,8),tt>>>((const float*)xhat, (size_t)128*2*NF, xt, xsF, 16640);
    hgemm<<<dim3(130,3,8),thr,HSM_TOT>>>(wq, xt, xsF, (float*)qkv, fsQ, 16640, 0, 0);
    fused_attn_kernel<<<1024,thr,SMEM_FFT>>>(qkv, tg, attn);
    tsplit<<<dim3(512,4,8),tt>>>(attn, psN, xt, xsN, NPIX);
    hgemm<<<dim3(128,1,8),thr,HSM_TOT>>>(wpj, xt, xsN, out, psN, NPIX, b_proj, 0);
}